// round 5
// baseline (speedup 1.0000x reference)
#include <cuda_runtime.h>
#include <cuda_bf16.h>
#include <cstdint>

#define ND 768
#define SZ (768*768)
#define MNTOT SZ
typedef long long ll;

// ---------------- scratch (device globals) ----------------------------------
__device__ float g_Tf[10*SZ];                         // fp32 T[side][k]
__device__ __align__(16) __nv_bfloat16 g_Tsh[10*SZ];  // split hi
__device__ __align__(16) __nv_bfloat16 g_Tsl[10*SZ];  // split lo
__device__ __align__(16) __nv_bfloat16 g_xTh[SZ];
__device__ __align__(16) __nv_bfloat16 g_xTl[SZ];
__device__ float g_Yf[4*SZ];                          // Y_1..Y_4 fp32
__device__ __align__(16) __nv_bfloat16 g_Ysh[5*SZ];   // slot0 = x split
__device__ __align__(16) __nv_bfloat16 g_Ysl[5*SZ];
__device__ float g_bff[20*SZ];
__device__ float g_h[32*SZ];
__device__ float g_c[32*SZ];

struct SrcPtrs { const float* p[25]; };

// ---------------- helpers -----------------------------------------------------
#define SWZ(x) ((x) ^ (((x) >> 3) & 0x70))

__device__ __forceinline__ uint32_t smem_u32(const void* p) {
  uint32_t a;
  asm("{ .reg .u64 t; cvta.to.shared.u64 t, %1; cvt.u32.u64 %0, t; }"
      : "=r"(a) : "l"(p));
  return a;
}

__device__ __forceinline__ void cpa16(uint32_t dst, const void* src) {
  asm volatile("cp.async.cg.shared.global [%0], [%1], 16;"
               :: "r"(dst), "l"(src) : "memory");
}
#define CP_COMMIT() asm volatile("cp.async.commit_group;" ::: "memory")
#define CP_WAIT(n)  asm volatile("cp.async.wait_group %0;" :: "n"(n) : "memory")

__device__ __forceinline__ void ldm4(uint32_t* r, uint32_t addr) {
  asm volatile("ldmatrix.sync.aligned.m8n8.x4.shared.b16 {%0,%1,%2,%3}, [%4];"
               : "=r"(r[0]), "=r"(r[1]), "=r"(r[2]), "=r"(r[3]) : "r"(addr));
}

__device__ __forceinline__ void mma16816(float* c, const uint32_t* a,
                                         const uint32_t* b) {
  asm volatile(
      "mma.sync.aligned.m16n8k16.row.col.f32.bf16.bf16.f32 "
      "{%0,%1,%2,%3},{%4,%5,%6,%7},{%8,%9},{%0,%1,%2,%3};"
      : "+f"(c[0]), "+f"(c[1]), "+f"(c[2]), "+f"(c[3])
      : "r"(a[0]), "r"(a[1]), "r"(a[2]), "r"(a[3]), "r"(b[0]), "r"(b[1]));
}

__device__ __forceinline__ uint32_t pack2(__nv_bfloat16 a, __nv_bfloat16 b) {
  __nv_bfloat162 t(a, b);
  return *reinterpret_cast<uint32_t*>(&t);
}

// load one 64-wide K chunk of 4 matrices (Ah[64],Al[64],Bh[128],Bl[128])
__device__ __forceinline__ void load_chunk(
    uint32_t sb, int s, int kc, int tid, int brow, int bcol,
    const __nv_bfloat16* a0, const __nv_bfloat16* a1,
    const __nv_bfloat16* b0, const __nv_bfloat16* b1)
{
  constexpr int ASTAGE = 64 * 128;     // 8 KB
  constexpr int STAGE  = 2 * ASTAGE + 32768;   // 48 KB
#pragma unroll
  for (int i = 0; i < 12; i++) {
    int idx = tid + i * 256;
    int c4 = idx & 7;
    int rowIdx = idx >> 3;
    const __nv_bfloat16* src;
    uint32_t dstbase;
    if (rowIdx < 128) {                 // uniform per i
      int mat = rowIdx >> 6;
      int row = rowIdx & 63;
      src = (mat ? a1 : a0) + (ll)(brow + row) * ND + kc * 64 + c4 * 8;
      dstbase = mat * ASTAGE + SWZ(row * 128 + c4 * 16);
    } else {
      int rr = rowIdx - 128;
      int mat = rr >> 7;
      int row = rr & 127;
      src = (mat ? b1 : b0) + (ll)(bcol + row) * ND + kc * 64 + c4 * 8;
      dstbase = 2 * ASTAGE + mat * 16384 + SWZ(row * 128 + c4 * 16);
    }
    cpa16(sb + s * STAGE + dstbase, src);
  }
}

// ---------------- tensor-core GEMM: C = alpha*A@B~^T + beta*Cin --------------
// Tile 64x128, 2 CTAs/SM. A,B fp32-as-split-bf16 (hi+lo). B~ is [N,K] K-major.
// offA = sAz*z + sAdiv*(z/adiv); offB = sBz*z + sBmod*(z%bmod)
// cinmode: 0 none, 1 identity (+beta on diagonal), 2 pointer
// Couth/Coutl non-null -> also emit split-bf16 copy of C (same sCz stride).
__global__ __launch_bounds__(256, 2) void tc_gemm(
    const __nv_bfloat16* __restrict__ Ah, const __nv_bfloat16* __restrict__ Al,
    const __nv_bfloat16* __restrict__ Bh, const __nv_bfloat16* __restrict__ Bl,
    const float* __restrict__ Cin, float* __restrict__ Cout,
    __nv_bfloat16* __restrict__ Couth, __nv_bfloat16* __restrict__ Coutl,
    ll sAz, ll sAdiv, int adiv,
    ll sBz, ll sBmod, int bmod,
    ll sCinz, ll sCz, float alpha, float beta, int cinmode)
{
  extern __shared__ char dsm[];
  constexpr int ASTAGE = 64 * 128;
  constexpr int STAGE  = 2 * ASTAGE + 32768;

  int z = blockIdx.z;
  ll offA = sAz * z + sAdiv * (z / adiv);
  ll offB = sBz * z + sBmod * (z % bmod);
  const __nv_bfloat16* ah = Ah + offA;
  const __nv_bfloat16* al = Al + offA;
  const __nv_bfloat16* bh = Bh + offB;
  const __nv_bfloat16* bl = Bl + offB;
  const int brow = blockIdx.y * 64;
  const int bcol = blockIdx.x * 128;

  int tid = threadIdx.x;
  int lane = tid & 31;
  int wid = tid >> 5;
  int wrow = (wid & 1) * 32;
  int wcol = (wid >> 1) * 32;

  uint32_t raw = smem_u32(dsm);
  uint32_t sb = (raw + 1023) & ~1023u;

  float acc[2][4][4];
#pragma unroll
  for (int mi = 0; mi < 2; mi++)
#pragma unroll
    for (int ni = 0; ni < 4; ni++)
#pragma unroll
      for (int e = 0; e < 4; e++) acc[mi][ni][e] = 0.0f;

  int a_r  = (lane & 7) + ((lane >> 3) & 1) * 8;
  int a_k8 = ((lane >> 4) & 1) * 8;
  int b_r  = (lane & 7) + ((lane >> 4) & 1) * 8;
  int b_k8 = ((lane >> 3) & 1) * 8;

  load_chunk(sb, 0, 0, tid, brow, bcol, ah, al, bh, bl); CP_COMMIT();
  load_chunk(sb, 1, 1, tid, brow, bcol, ah, al, bh, bl); CP_COMMIT();

  for (int kc = 0; kc < 12; kc++) {
    if (kc < 11) { CP_WAIT(1); } else { CP_WAIT(0); }
    __syncthreads();

    uint32_t st  = sb + (kc & 1) * STAGE;
    uint32_t tAh = st;
    uint32_t tAl = st + ASTAGE;
    uint32_t tBh = st + 2 * ASTAGE;
    uint32_t tBl = tBh + 16384;

#pragma unroll
    for (int s = 0; s < 4; s++) {
      uint32_t fah[2][4], fal[2][4];
#pragma unroll
      for (int mi = 0; mi < 2; mi++) {
        int r = wrow + mi * 16 + a_r;
        uint32_t off = SWZ(r * 128 + (s * 16 + a_k8) * 2);
        ldm4(fah[mi], tAh + off);
        ldm4(fal[mi], tAl + off);
      }
      uint32_t fbh[4][2], fbl[4][2];
#pragma unroll
      for (int nj = 0; nj < 2; nj++) {
        int r = wcol + nj * 16 + b_r;
        uint32_t off = SWZ(r * 128 + (s * 16 + b_k8) * 2);
        uint32_t t4[4];
        ldm4(t4, tBh + off);
        fbh[nj * 2][0] = t4[0]; fbh[nj * 2][1] = t4[1];
        fbh[nj * 2 + 1][0] = t4[2]; fbh[nj * 2 + 1][1] = t4[3];
        ldm4(t4, tBl + off);
        fbl[nj * 2][0] = t4[0]; fbl[nj * 2][1] = t4[1];
        fbl[nj * 2 + 1][0] = t4[2]; fbl[nj * 2 + 1][1] = t4[3];
      }
#pragma unroll
      for (int mi = 0; mi < 2; mi++)
#pragma unroll
        for (int ni = 0; ni < 4; ni++)
          mma16816(acc[mi][ni], fah[mi], fbh[ni]);
#pragma unroll
      for (int mi = 0; mi < 2; mi++)
#pragma unroll
        for (int ni = 0; ni < 4; ni++)
          mma16816(acc[mi][ni], fah[mi], fbl[ni]);
#pragma unroll
      for (int mi = 0; mi < 2; mi++)
#pragma unroll
        for (int ni = 0; ni < 4; ni++)
          mma16816(acc[mi][ni], fal[mi], fbh[ni]);
    }

    __syncthreads();
    if (kc + 2 < 12) {
      load_chunk(sb, kc & 1, kc + 2, tid, brow, bcol, ah, al, bh, bl);
      CP_COMMIT();
    }
  }

  // ---- epilogue: registers -> gmem (fp32 + optional split bf16) -------------
  const float* cinp = (cinmode == 2) ? (Cin + sCinz * z) : (const float*)0;
  float* co = Cout + sCz * z;
  __nv_bfloat16* coh = Couth ? (Couth + sCz * z) : (__nv_bfloat16*)0;
  __nv_bfloat16* col = Coutl ? (Coutl + sCz * z) : (__nv_bfloat16*)0;
  int qr = lane >> 2, qc = lane & 3;

#pragma unroll
  for (int mi = 0; mi < 2; mi++) {
#pragma unroll
    for (int ni = 0; ni < 4; ni++) {
      int gr0 = brow + wrow + mi * 16 + qr;
      int gc  = bcol + wcol + ni * 8 + qc * 2;
      float2 v0, v1;
      v0.x = alpha * acc[mi][ni][0];
      v0.y = alpha * acc[mi][ni][1];
      v1.x = alpha * acc[mi][ni][2];
      v1.y = alpha * acc[mi][ni][3];
      if (cinmode == 2) {
        float2 c0 = *(const float2*)&cinp[(ll)gr0 * ND + gc];
        float2 c1 = *(const float2*)&cinp[(ll)(gr0 + 8) * ND + gc];
        v0.x += beta * c0.x; v0.y += beta * c0.y;
        v1.x += beta * c1.x; v1.y += beta * c1.y;
      } else if (cinmode == 1) {
        if (gr0 == gc)         v0.x += beta;
        if (gr0 == gc + 1)     v0.y += beta;
        if (gr0 + 8 == gc)     v1.x += beta;
        if (gr0 + 8 == gc + 1) v1.y += beta;
      }
      *(float2*)&co[(ll)gr0 * ND + gc]       = v0;
      *(float2*)&co[(ll)(gr0 + 8) * ND + gc] = v1;
      if (coh) {
        __nv_bfloat16 h0 = __float2bfloat16(v0.x);
        __nv_bfloat16 h1 = __float2bfloat16(v0.y);
        __nv_bfloat16 h2 = __float2bfloat16(v1.x);
        __nv_bfloat16 h3 = __float2bfloat16(v1.y);
        *(uint32_t*)&coh[(ll)gr0 * ND + gc]       = pack2(h0, h1);
        *(uint32_t*)&coh[(ll)(gr0 + 8) * ND + gc] = pack2(h2, h3);
        *(uint32_t*)&col[(ll)gr0 * ND + gc] =
            pack2(__float2bfloat16(v0.x - __bfloat162float(h0)),
                  __float2bfloat16(v0.y - __bfloat162float(h1)));
        *(uint32_t*)&col[(ll)(gr0 + 8) * ND + gc] =
            pack2(__float2bfloat16(v1.x - __bfloat162float(h2)),
                  __float2bfloat16(v1.y - __bfloat162float(h3)));
      }
    }
  }
}

// ---------------- fp32 -> split bf16 (setup only) ----------------------------
__global__ __launch_bounds__(256) void split_kernel(
    const float* __restrict__ src, __nv_bfloat16* __restrict__ hi,
    __nv_bfloat16* __restrict__ lo, ll sS, ll sD)
{
  ll so = sS * blockIdx.z, dofs = sD * blockIdx.z;
  int idx = blockIdx.x * 256 + threadIdx.x;
  float4 v = *(const float4*)(src + so + (ll)idx * 4);
  float a[4] = {v.x, v.y, v.z, v.w};
  __nv_bfloat16 h[4], l[4];
#pragma unroll
  for (int e = 0; e < 4; e++) {
    h[e] = __float2bfloat16(a[e]);
    l[e] = __float2bfloat16(a[e] - __bfloat162float(h[e]));
  }
  uint2 uh, ul;
  uh.x = pack2(h[0], h[1]); uh.y = pack2(h[2], h[3]);
  ul.x = pack2(l[0], l[1]); ul.y = pack2(l[2], l[3]);
  *(uint2*)(hi + dofs + (ll)idx * 4) = uh;
  *(uint2*)(lo + dofs + (ll)idx * 4) = ul;
}

// ---------------- transpose + split: xT = x^T --------------------------------
__global__ void tsplit_kernel(const float* __restrict__ src,
                              __nv_bfloat16* __restrict__ th,
                              __nv_bfloat16* __restrict__ tl)
{
  __shared__ float t[32][33];
  int bx = blockIdx.x * 32, by = blockIdx.y * 32;
  int tx = threadIdx.x, ty = threadIdx.y;
#pragma unroll
  for (int i = 0; i < 4; i++)
    t[ty + 8 * i][tx] = src[(ll)(by + ty + 8 * i) * ND + bx + tx];
  __syncthreads();
#pragma unroll
  for (int i = 0; i < 4; i++) {
    float a = t[tx][ty + 8 * i];
    __nv_bfloat16 h = __float2bfloat16(a);
    __nv_bfloat16 l = __float2bfloat16(a - __bfloat162float(h));
    ll o = (ll)(bx + ty + 8 * i) * ND + by + tx;
    th[o] = h;
    tl[o] = l;
  }
}

// ---------------- fused conv-combine + LSTM gates + dx + x-split -------------
__device__ __forceinline__ float sigf(float v) {
  return __fdividef(1.0f, 1.0f + __expf(-v));
}

__global__ __launch_bounds__(256) void fused_rnn(
    SrcPtrs srcs, const float* __restrict__ theta, const float* __restrict__ bias,
    const float* __restrict__ Wf, const float* __restrict__ Uf, const float* __restrict__ bf_,
    const float* __restrict__ Wi, const float* __restrict__ Ui, const float* __restrict__ bi_,
    const float* __restrict__ Wo, const float* __restrict__ Uo, const float* __restrict__ bo_,
    const float* __restrict__ Wc, const float* __restrict__ Uc, const float* __restrict__ bc_,
    const float* __restrict__ Wout, const float* __restrict__ bout,
    float* h, float* c, float* x,
    __nv_bfloat16* __restrict__ xsh, __nv_bfloat16* __restrict__ xsl,
    int first, int last)
{
  extern __shared__ float ds[];
  float* th  = ds;           // 800
  float* bs  = ds + 800;     // 32
  float* swo = ds + 832;     // 32
  float* sbg = ds + 864;     // 128
  float* sW  = ds + 992;     // 4096
  float* sU  = ds + 5088;    // 4096
  float* sxc = ds + 9184;    // 4096
  float* sdx = ds + 13280;   // 128*9

  int t = threadIdx.x;
  for (int i = t; i < 800; i += 256) th[i] = theta[i];
  if (t < 32) { bs[t] = bias[t]; swo[t] = Wout[t]; }
  {
    const float* Ws[4] = {Wf, Wi, Wo, Wc};
    const float* Us[4] = {Uf, Ui, Uo, Uc};
    for (int idx = t; idx < 4096; idx += 256) {
      int k = idx >> 7, g = (idx >> 5) & 3, o = idx & 31;
      sW[(k * 4 + g) * 32 + o] = Ws[g][k * 32 + o];
      if (!first) sU[(k * 4 + g) * 32 + o] = Us[g][k * 32 + o];
    }
    if (t < 128) { const float* bx[4] = {bf_, bi_, bo_, bc_}; sbg[t] = bx[t >> 5][t & 31]; }
  }
  __syncthreads();

  // ---- phase 1: conv combine -> sxc[k][r]
  {
    int r  = t & 127;
    int oh = (t >> 7) * 16;
    size_t rg = (size_t)blockIdx.x * 128 + r;
    float out[16];
#pragma unroll
    for (int o = 0; o < 16; o++) out[o] = bs[oh + o];
#pragma unroll
    for (int ij = 0; ij < 25; ij++) {
      float v = __ldg(srcs.p[ij] + rg);
      const float* tw = &th[ij * 32 + oh];
#pragma unroll
      for (int o = 0; o < 16; o++) out[o] += v * tw[o];
    }
#pragma unroll
    for (int o = 0; o < 16; o++) sxc[(oh + o) * 128 + r] = out[o];
  }
  __syncthreads();

  // ---- phase 2: gate GEMM (K=32)
  int rt = t & 31, ot = t >> 5;
  size_t r0 = (size_t)blockIdx.x * 128 + rt * 4;
  int ob = ot * 4;

  float acc[4][4][4];
#pragma unroll
  for (int o = 0; o < 4; o++)
#pragma unroll
    for (int g = 0; g < 4; g++)
#pragma unroll
      for (int rr = 0; rr < 4; rr++) acc[o][g][rr] = 0.0f;

  if (first) {
#pragma unroll 4
    for (int k = 0; k < 32; k++) {
      float4 xv = *(const float4*)&sxc[k * 128 + rt * 4];
      float xr[4] = {xv.x, xv.y, xv.z, xv.w};
#pragma unroll
      for (int g = 0; g < 4; g++) {
        float4 w4 = *(const float4*)&sW[(k * 4 + g) * 32 + ob];
        float w[4] = {w4.x, w4.y, w4.z, w4.w};
#pragma unroll
        for (int o = 0; o < 4; o++)
#pragma unroll
          for (int rr = 0; rr < 4; rr++)
            acc[o][g][rr] += w[o] * xr[rr];
      }
    }
  } else {
#pragma unroll 4
    for (int k = 0; k < 32; k++) {
      float4 xv = *(const float4*)&sxc[k * 128 + rt * 4];
      float4 hv = *(const float4*)&h[(size_t)k * MNTOT + r0];
      float xr[4] = {xv.x, xv.y, xv.z, xv.w};
      float hr[4] = {hv.x, hv.y, hv.z, hv.w};
#pragma unroll
      for (int g = 0; g < 4; g++) {
        float4 w4 = *(const float4*)&sW[(k * 4 + g) * 32 + ob];
        float4 u4 = *(const float4*)&sU[(k * 4 + g) * 32 + ob];
        float w[4] = {w4.x, w4.y, w4.z, w4.w};
        float u[4] = {u4.x, u4.y, u4.z, u4.w};
#pragma unroll
        for (int o = 0; o < 4; o++)
#pragma unroll
          for (int rr = 0; rr < 4; rr++)
            acc[o][g][rr] += w[o] * xr[rr] + u[o] * hr[rr];
      }
    }
  }
  __syncthreads();

  // ---- phase 3: epilogue + dx partials
  float pd[4] = {0.0f, 0.0f, 0.0f, 0.0f};
#pragma unroll
  for (int o = 0; o < 4; o++) {
    int oo = ob + o;
    float co[4] = {0.0f, 0.0f, 0.0f, 0.0f};
    if (!first) {
      float4 c4 = *(const float4*)&c[(size_t)oo * MNTOT + r0];
      co[0] = c4.x; co[1] = c4.y; co[2] = c4.z; co[3] = c4.w;
    }
    float cn[4], hn[4];
#pragma unroll
    for (int rr = 0; rr < 4; rr++) {
      float ig = sigf(acc[o][1][rr] + sbg[32 + oo]);
      float cu = sigf(acc[o][3][rr] + sbg[96 + oo]);
      float cnew = ig * cu;
      if (!first) {
        float fg = sigf(acc[o][0][rr] + sbg[oo]);
        cnew += fg * co[rr];
      }
      cn[rr] = cnew;
      pd[rr] += cnew * swo[oo];
      if (!last) {
        float og = sigf(acc[o][2][rr] + sbg[64 + oo]);
        hn[rr] = og * sigf(cnew);
      }
    }
    if (!last) {
      float4 cv; cv.x = cn[0]; cv.y = cn[1]; cv.z = cn[2]; cv.w = cn[3];
      float4 hv; hv.x = hn[0]; hv.y = hn[1]; hv.z = hn[2]; hv.w = hn[3];
      *(float4*)&c[(size_t)oo * MNTOT + r0] = cv;
      *(float4*)&h[(size_t)oo * MNTOT + r0] = hv;
    }
  }
#pragma unroll
  for (int rr = 0; rr < 4; rr++)
    sdx[(rt * 4 + rr) * 9 + ot] = pd[rr];
  __syncthreads();

  if (t < 128) {
    float s = __ldg(bout);
#pragma unroll
    for (int o2 = 0; o2 < 8; o2++) s += sdx[t * 9 + o2];
    size_t gi = (size_t)blockIdx.x * 128 + t;
    float xn = x[gi] + tanhf(s);
    x[gi] = xn;
    if (!last) {
      __nv_bfloat16 hh = __float2bfloat16(xn);
      xsh[gi] = hh;
      xsl[gi] = __float2bfloat16(xn - __bfloat162float(hh));
    }
  }
}

// ---------------- orchestration ----------------------------------------------
extern "C" void kernel_launch(void* const* d_in, const int* in_sizes, int n_in,
                              void* d_out, int out_size)
{
  const float* x     = (const float*)d_in[0];
  const float* L_row = (const float*)d_in[1];
  const float* L_col = (const float*)d_in[2];
  const float* theta = (const float*)d_in[3];
  const float* bias  = (const float*)d_in[4];
  const float* W_f = (const float*)d_in[5];
  const float* U_f = (const float*)d_in[6];
  const float* b_f = (const float*)d_in[7];
  const float* W_i = (const float*)d_in[8];
  const float* U_i = (const float*)d_in[9];
  const float* b_i = (const float*)d_in[10];
  const float* W_o = (const float*)d_in[11];
  const float* U_o = (const float*)d_in[12];
  const float* b_o = (const float*)d_in[13];
  const float* W_c = (const float*)d_in[14];
  const float* U_c = (const float*)d_in[15];
  const float* b_c = (const float*)d_in[16];
  const float* W_out = (const float*)d_in[17];
  const float* b_out = (const float*)d_in[18];
  // d_in[19] = nb_iterations_rnn = 3 (fixed by setup)

  float* xcur = (float*)d_out;

  float *Tf, *Yf, *bff, *h, *c;
  __nv_bfloat16 *Tsh, *Tsl, *xTh, *xTl, *Ysh, *Ysl;
  cudaGetSymbolAddress((void**)&Tf,  g_Tf);
  cudaGetSymbolAddress((void**)&Tsh, g_Tsh);
  cudaGetSymbolAddress((void**)&Tsl, g_Tsl);
  cudaGetSymbolAddress((void**)&xTh, g_xTh);
  cudaGetSymbolAddress((void**)&xTl, g_xTl);
  cudaGetSymbolAddress((void**)&Yf,  g_Yf);
  cudaGetSymbolAddress((void**)&Ysh, g_Ysh);
  cudaGetSymbolAddress((void**)&Ysl, g_Ysl);
  cudaGetSymbolAddress((void**)&bff, g_bff);
  cudaGetSymbolAddress((void**)&h,   g_h);
  cudaGetSymbolAddress((void**)&c,   g_c);

  const ll S = SZ;
  const int DSM = 1024 + 2 * 49152;    // 2-stage, 64x128 tile -> 2 CTAs/SM
  const int FSM = (800 + 32 + 32 + 128 + 4096 * 3 + 128 * 9) * 4;
  cudaFuncSetAttribute(tc_gemm,   cudaFuncAttributeMaxDynamicSharedMemorySize, DSM);
  cudaFuncSetAttribute(fused_rnn, cudaFuncAttributeMaxDynamicSharedMemorySize, FSM);

  cudaMemcpyAsync(xcur, x, SZ * sizeof(float), cudaMemcpyDeviceToDevice);
  cudaMemcpyAsync(Tf + 1 * S, L_row, SZ * sizeof(float), cudaMemcpyDeviceToDevice);
  cudaMemcpyAsync(Tf + 6 * S, L_col, SZ * sizeof(float), cudaMemcpyDeviceToDevice);
  {
    dim3 g(SZ / 1024, 1, 2);
    split_kernel<<<g, 256>>>(Tf + S, Tsh + S, Tsl + S, 5 * S, 5 * S);
  }
  {  // x split -> Ys slot 0 (bf-GEMM A operand for i=0)
    dim3 g(SZ / 1024, 1, 1);
    split_kernel<<<g, 256>>>(xcur, Ysh, Ysl, 0, 0);
  }

  // Chebyshev: T_k = 2*L@T_{k-1} - T_{k-2}; epilogue emits fp32 + split
  for (int k = 2; k <= 4; k++) {
    dim3 g(6, 12, 2);
    int cinmode = (k == 2) ? 1 : 2;
    const float* cin = (k == 2) ? (const float*)0 : (Tf + (ll)(k - 2) * S);
    tc_gemm<<<g, 256, DSM>>>(
        Tsh + S, Tsl + S,
        Tsh + (ll)(k - 1) * S, Tsl + (ll)(k - 1) * S,
        cin, Tf + (ll)k * S, Tsh + (ll)k * S, Tsl + (ll)k * S,
        5 * S, 0, 1,
        5 * S, 0, 1,
        5 * S, 5 * S, 2.0f, -1.0f, cinmode);
  }

  SrcPtrs sp;
  for (int i = 0; i < 5; i++)
    for (int j = 0; j < 5; j++)
      sp.p[i * 5 + j] = (j == 0)
          ? ((i == 0) ? (const float*)xcur : (Yf + (ll)(i - 1) * S))
          : (bff + (ll)(i * 4 + j - 1) * S);

  for (int it = 0; it < 3; it++) {
    {
      dim3 g(24, 24);
      dim3 b(32, 8);
      tsplit_kernel<<<g, b>>>(xcur, xTh, xTl);
    }
    // Y_{1+z} = Tr_{1+z} @ x (B~ = x^T); epilogue emits Yf + Ys split slots 1..4
    {
      dim3 g(6, 12, 4);
      tc_gemm<<<g, 256, DSM>>>(
          Tsh + S, Tsl + S, xTh, xTl,
          (const float*)0, Yf, Ysh + S, Ysl + S,
          S, 0, 1,    0, 0, 1,
          0, S, 1.0f, 0.0f, 0);
    }
    // bf[z] = Y_{z/4} @ Tc_{1+z%4}  (Ys slot 0 = x split), z = 0..19
    {
      dim3 g(6, 12, 20);
      tc_gemm<<<g, 256, DSM>>>(
          Ysh, Ysl, Tsh + 6 * S, Tsl + 6 * S,
          (const float*)0, bff, (__nv_bfloat16*)0, (__nv_bfloat16*)0,
          0, S, 4,    0, S, 4,
          0, S, 1.0f, 0.0f, 0);
    }
    fused_rnn<<<SZ / 128, 256, FSM>>>(
        sp, theta, bias,
        W_f, U_f, b_f, W_i, U_i, b_i, W_o, U_o, b_o, W_c, U_c, b_c,
        W_out, b_out, h, c, xcur, Ysh, Ysl,
        (it == 0) ? 1 : 0, (it == 2) ? 1 : 0);
  }
}